// round 3
// baseline (speedup 1.0000x reference)
#include <cuda_runtime.h>
#include <cstdint>

#define THRESHOLD 0.01f
#define D 768
#define D4 (D / 4)               // 192 float4 per row
#define ROW_BYTES (D * 4)        // 3072 bytes per row
#define NTOK (8 * 2048)          // 16384 tokens
#define TPC 8                    // tokens per CTA (= pipeline stages)
#define STAGE_BYTES (2 * ROW_BYTES)          // mask row + weight row = 6144
#define SMEM_DATA (TPC * STAGE_BYTES)        // 49152
#define SMEM_BYTES (SMEM_DATA + TPC * 8)     // + mbarriers

__device__ __forceinline__ uint32_t smem_u32(const void* p) {
    return (uint32_t)__cvta_generic_to_shared(p);
}

__global__ __launch_bounds__(D4)
void masked_embedding_bulk_kernel(const int* __restrict__ x,
                                  const char* __restrict__ mask,
                                  const char* __restrict__ weight,
                                  float4* __restrict__ out) {
    extern __shared__ char smem[];
    const int tid = threadIdx.x;               // 0..191
    const long long token0 = (long long)blockIdx.x * TPC;

    uint32_t sbase = smem_u32(smem);
    uint32_t bar_base = sbase + SMEM_DATA;

    // Init one mbarrier per stage (arrive count 1; completion is tx-based).
    if (tid == 0) {
#pragma unroll
        for (int s = 0; s < TPC; s++) {
            asm volatile("mbarrier.init.shared::cta.b64 [%0], %1;"
                         :: "r"(bar_base + s * 8), "r"(1) : "memory");
        }
    }
    // Make mbarrier init visible to the async proxy before any bulk copy.
    asm volatile("fence.proxy.async.shared::cta;" ::: "memory");
    __syncthreads();

    // Lanes 0..7 each launch the two 3KB bulk copies for one token.
    if (tid < TPC) {
        const int row = __ldg(&x[token0 + tid]);
        const char* msrc = mask + (size_t)row * ROW_BYTES;
        const char* wsrc = weight + (size_t)row * ROW_BYTES;
        uint32_t bar = bar_base + tid * 8;
        uint32_t dst = sbase + tid * STAGE_BYTES;

        asm volatile("mbarrier.arrive.expect_tx.shared::cta.b64 _, [%0], %1;"
                     :: "r"(bar), "r"((uint32_t)STAGE_BYTES) : "memory");
        asm volatile("cp.async.bulk.shared::cta.global.mbarrier::complete_tx::bytes "
                     "[%0], [%1], %2, [%3];"
                     :: "r"(dst), "l"(msrc), "r"((uint32_t)ROW_BYTES), "r"(bar) : "memory");
        asm volatile("cp.async.bulk.shared::cta.global.mbarrier::complete_tx::bytes "
                     "[%0], [%1], %2, [%3];"
                     :: "r"(dst + ROW_BYTES), "l"(wsrc), "r"((uint32_t)ROW_BYTES), "r"(bar) : "memory");
    }

    // Consume stages in order; all copies are already in flight (depth = 8).
#pragma unroll
    for (int t = 0; t < TPC; t++) {
        uint32_t bar = bar_base + t * 8;
        uint32_t done;
        asm volatile(
            "{\n\t"
            ".reg .pred p;\n\t"
            "mbarrier.try_wait.parity.acquire.cta.shared::cta.b64 p, [%1], 0;\n\t"
            "selp.b32 %0, 1, 0, p;\n\t"
            "}" : "=r"(done) : "r"(bar) : "memory");
        if (!done) {
            asm volatile(
                "{\n\t"
                ".reg .pred P1;\n\t"
                "WAIT_LOOP_%=:\n\t"
                "mbarrier.try_wait.parity.acquire.cta.shared::cta.b64 P1, [%0], 0, 0x989680;\n\t"
                "@P1 bra.uni WAIT_DONE_%=;\n\t"
                "bra.uni WAIT_LOOP_%=;\n\t"
                "WAIT_DONE_%=:\n\t"
                "}" :: "r"(bar) : "memory");
        }

        const float4* sm = (const float4*)(smem + t * STAGE_BYTES);
        const float4* sw = (const float4*)(smem + t * STAGE_BYTES + ROW_BYTES);
        float4 m = sm[tid];
        float4 w = sw[tid];

        float4 o;
        o.x = (m.x > THRESHOLD) ? w.x : 0.0f;
        o.y = (m.y > THRESHOLD) ? w.y : 0.0f;
        o.z = (m.z > THRESHOLD) ? w.z : 0.0f;
        o.w = (m.w > THRESHOLD) ? w.w : 0.0f;

        __stcs(&out[(token0 + t) * D4 + tid], o);
    }
}

extern "C" void kernel_launch(void* const* d_in, const int* in_sizes, int n_in,
                              void* d_out, int out_size) {
    const int*  x      = (const int*)d_in[0];
    const char* mask   = (const char*)d_in[1];
    const char* weight = (const char*)d_in[2];
    float4*     out    = (float4*)d_out;

    static bool attr_set = false;
    if (!attr_set) {
        cudaFuncSetAttribute(masked_embedding_bulk_kernel,
                             cudaFuncAttributeMaxDynamicSharedMemorySize, SMEM_BYTES);
        attr_set = true;
    }

    masked_embedding_bulk_kernel<<<NTOK / TPC, D4, SMEM_BYTES>>>(x, mask, weight, out);
}

// round 5
// speedup vs baseline: 1.0414x; 1.0414x over previous
#include <cuda_runtime.h>

#define THRESHOLD 0.01f
#define D 768
#define D4 (D / 4)            // 192 float4 per row
#define NTOK (8 * 2048)       // 16384 tokens
#define TPB 4                 // tokens per block

__device__ __forceinline__ unsigned long long evict_last_policy() {
    unsigned long long pol;
    asm("createpolicy.fractional.L2::evict_last.b64 %0, 1.0;" : "=l"(pol));
    return pol;
}

__device__ __forceinline__ float4 ldg_evict_last(const float4* p, unsigned long long pol) {
    float4 v;
    asm volatile("ld.global.nc.L2::cache_hint.v4.f32 {%0,%1,%2,%3}, [%4], %5;"
                 : "=f"(v.x), "=f"(v.y), "=f"(v.z), "=f"(v.w)
                 : "l"(p), "l"(pol));
    return v;
}

__global__ __launch_bounds__(D4)
void masked_embedding_kernel(const int* __restrict__ x,
                             const float4* __restrict__ mask,
                             const float4* __restrict__ weight,
                             float4* __restrict__ out) {
    const int token0 = blockIdx.x * TPB;
    const int c = threadIdx.x;                 // 0..191
    const unsigned long long pol = evict_last_policy();

    int rows[TPB];
#pragma unroll
    for (int i = 0; i < TPB; i++)
        rows[i] = __ldg(&x[token0 + i]);

    // Front-batch 8 independent 16B loads; table reads hinted evict_last so the
    // ~84MB distinct-row working set stays L2-resident across graph replays.
    float4 m[TPB], w[TPB];
#pragma unroll
    for (int i = 0; i < TPB; i++) {
        const long long src = (long long)rows[i] * D4 + c;
        m[i] = ldg_evict_last(&mask[src], pol);
        w[i] = ldg_evict_last(&weight[src], pol);
    }

#pragma unroll
    for (int i = 0; i < TPB; i++) {
        float4 o;
        o.x = (m[i].x > THRESHOLD) ? w[i].x : 0.0f;
        o.y = (m[i].y > THRESHOLD) ? w[i].y : 0.0f;
        o.z = (m[i].z > THRESHOLD) ? w[i].z : 0.0f;
        o.w = (m[i].w > THRESHOLD) ? w[i].w : 0.0f;
        // Output has zero reuse: streaming (evict-first) store.
        __stcs(&out[(long long)(token0 + i) * D4 + c], o);
    }
}

extern "C" void kernel_launch(void* const* d_in, const int* in_sizes, int n_in,
                              void* d_out, int out_size) {
    const int*    x      = (const int*)d_in[0];
    const float4* mask   = (const float4*)d_in[1];
    const float4* weight = (const float4*)d_in[2];
    float4*       out    = (float4*)d_out;

    masked_embedding_kernel<<<NTOK / TPB, D4>>>(x, mask, weight, out);
}